// round 1
// baseline (speedup 1.0000x reference)
#include <cuda_runtime.h>
#include <math.h>
#include <stdint.h>

// Problem constants (fixed shapes)
#define Nn    20000
#define Ee    640000
#define ETOT  (Ee + Nn)
#define Gg    64
#define DIN   256
#define Hh    4
#define Cc    64
#define HC    256
#define DOUT  32

// ---------------- scratch (device globals; no allocation) ----------------
__device__ __align__(16) float g_h[Nn * HC];    // GEMM output (pre-activation h)
__device__ __align__(16) float g_x[Nn * HC];    // layer output (x1, then x2)
__device__ __align__(16) float g_es[Nn * Hh];
__device__ __align__(16) float g_ed[Nn * Hh];
__device__ int   g_deg[Nn];
__device__ int   g_off[Nn + 1];
__device__ int   g_cur[Nn];
__device__ int   g_csr[ETOT];
__device__ float g_sums[Gg * DOUT];
__device__ int   g_cnt[Gg];

// ---------------- helpers ----------------
__device__ __forceinline__ float lrelu(float x) { return x > 0.0f ? x : 0.2f * x; }

__device__ __forceinline__ unsigned long long dup2(float v) {
    unsigned int u = __float_as_uint(v);
    return ((unsigned long long)u << 32) | (unsigned long long)u;
}

#define FMA2(d, a, b) asm("fma.rn.f32x2 %0, %1, %2, %0;" : "+l"(d) : "l"(a), "l"(b))

// ---------------- zero scratch ----------------
__global__ void k_zero() {
    int i = blockIdx.x * blockDim.x + threadIdx.x;
    if (i < Nn) g_deg[i] = 0;
    if (i < Gg * DOUT) g_sums[i] = 0.0f;
    if (i < Gg) g_cnt[i] = 0;
}

// ---------------- CSR build ----------------
__global__ void k_count(const int* __restrict__ ei) {
    int e = blockIdx.x * blockDim.x + threadIdx.x;
    if (e >= ETOT) return;
    int d = (e < Ee) ? ei[Ee + e] : (e - Ee);
    atomicAdd(&g_deg[d], 1);
}

__global__ void k_scan() {
    __shared__ int sh[1024];
    const int CH = (Nn + 1023) / 1024;  // 20
    int t = threadIdx.x;
    int base = t * CH;
    int s = 0;
#pragma unroll
    for (int i = 0; i < CH; i++) {
        int idx = base + i;
        if (idx < Nn) s += g_deg[idx];
    }
    sh[t] = s;
    __syncthreads();
    for (int off = 1; off < 1024; off <<= 1) {
        int v = 0;
        if (t >= off) v = sh[t - off];
        __syncthreads();
        sh[t] += v;
        __syncthreads();
    }
    int run = sh[t] - s;  // exclusive prefix
#pragma unroll
    for (int i = 0; i < CH; i++) {
        int idx = base + i;
        if (idx < Nn) {
            g_off[idx] = run;
            g_cur[idx] = run;
            run += g_deg[idx];
        }
    }
    if (t == 1023) g_off[Nn] = sh[1023];
}

__global__ void k_scatter(const int* __restrict__ ei) {
    int e = blockIdx.x * blockDim.x + threadIdx.x;
    if (e >= ETOT) return;
    int s, d;
    if (e < Ee) { s = ei[e]; d = ei[Ee + e]; }
    else        { s = e - Ee; d = s; }
    int p = atomicAdd(&g_cur[d], 1);
    g_csr[p] = s;
}

// ---------------- GEMM: C[M,256] = A[M,256] @ B[256,256], fp32, f32x2 FMA ----------
// Block tile 128x64, K-tile 16, 256 threads, 8x4 per thread (as 4 m-pairs x 4 n).
#define BM 128
#define BN 64
#define BK 16

__global__ void __launch_bounds__(256) k_gemm(const float* __restrict__ A_ext,
                                              const float* __restrict__ B,
                                              int useExt) {
    const float* __restrict__ A = useExt ? A_ext : g_x;
    float* __restrict__ C = g_h;

    __shared__ __align__(16) float As[BK][BM];
    __shared__ __align__(16) unsigned long long Bs[BK][BN];  // value duplicated in both halves

    int tid = threadIdx.x;
    int bm = blockIdx.x * BM;
    int bn = blockIdx.y * BN;
    int tm = tid >> 4;      // 0..15 -> 8 rows each
    int tn = tid & 15;      // 0..15 -> 4 cols each

    unsigned long long acc[4][4];
#pragma unroll
    for (int i = 0; i < 4; i++)
#pragma unroll
        for (int j = 0; j < 4; j++) acc[i][j] = 0ULL;

    int lm = tid & 127;          // A-load row within tile
    int lks = (tid >> 7) * 8;    // A-load k segment (0 or 8)
    int lkb = tid >> 4;          // B-load k row
    int ln0 = (tid & 15) * 4;    // B-load n start

    for (int k0 = 0; k0 < 256; k0 += BK) {
        // load A tile (transposed into As[k][m])
        float4 va0 = make_float4(0.f, 0.f, 0.f, 0.f);
        float4 va1 = va0;
        if (bm + lm < Nn) {
            const float* Ap = A + (size_t)(bm + lm) * HC + k0 + lks;
            va0 = *(const float4*)Ap;
            va1 = *(const float4*)(Ap + 4);
        }
        As[lks + 0][lm] = va0.x; As[lks + 1][lm] = va0.y;
        As[lks + 2][lm] = va0.z; As[lks + 3][lm] = va0.w;
        As[lks + 4][lm] = va1.x; As[lks + 5][lm] = va1.y;
        As[lks + 6][lm] = va1.z; As[lks + 7][lm] = va1.w;

        // load B tile (duplicate each value into a u64 pair)
        float4 vb = *(const float4*)(B + (size_t)(k0 + lkb) * HC + bn + ln0);
        Bs[lkb][ln0 + 0] = dup2(vb.x);
        Bs[lkb][ln0 + 1] = dup2(vb.y);
        Bs[lkb][ln0 + 2] = dup2(vb.z);
        Bs[lkb][ln0 + 3] = dup2(vb.w);

        __syncthreads();

#pragma unroll
        for (int kk = 0; kk < BK; kk++) {
            ulonglong2 a0 = *(const ulonglong2*)&As[kk][tm * 8];
            ulonglong2 a1 = *(const ulonglong2*)&As[kk][tm * 8 + 4];
            unsigned long long ar[4] = {a0.x, a0.y, a1.x, a1.y};
#pragma unroll
            for (int j = 0; j < 4; j++) {
                unsigned long long b = Bs[kk][tn * 4 + j];
                FMA2(acc[0][j], ar[0], b);
                FMA2(acc[1][j], ar[1], b);
                FMA2(acc[2][j], ar[2], b);
                FMA2(acc[3][j], ar[3], b);
            }
        }
        __syncthreads();
    }

    // epilogue
#pragma unroll
    for (int p = 0; p < 4; p++) {
        int row = bm + tm * 8 + p * 2;
        float4 lo, hi;
        lo.x = __uint_as_float((unsigned)acc[p][0]); hi.x = __uint_as_float((unsigned)(acc[p][0] >> 32));
        lo.y = __uint_as_float((unsigned)acc[p][1]); hi.y = __uint_as_float((unsigned)(acc[p][1] >> 32));
        lo.z = __uint_as_float((unsigned)acc[p][2]); hi.z = __uint_as_float((unsigned)(acc[p][2] >> 32));
        lo.w = __uint_as_float((unsigned)acc[p][3]); hi.w = __uint_as_float((unsigned)(acc[p][3] >> 32));
        if (row < Nn)     *(float4*)&C[(size_t)row * HC + bn + tn * 4] = lo;
        if (row + 1 < Nn) *(float4*)&C[(size_t)(row + 1) * HC + bn + tn * 4] = hi;
    }
}

// ---------------- attention source/dst scores: es/ed[n,h] = <h[n,h,:], a[h,:]> ------
__global__ void k_attn(const float* __restrict__ asrc, const float* __restrict__ adst) {
    int w = (blockIdx.x * blockDim.x + threadIdx.x) >> 5;
    if (w >= Nn) return;
    int lane = threadIdx.x & 31;

    const float4* hp = (const float4*)(g_h + (size_t)w * HC + lane * 8);
    float4 v0 = hp[0], v1 = hp[1];
    const float4* sp = (const float4*)(asrc + lane * 8);
    float4 s0 = sp[0], s1 = sp[1];
    const float4* dp = (const float4*)(adst + lane * 8);
    float4 d0 = dp[0], d1 = dp[1];

    float ps = v0.x * s0.x + v0.y * s0.y + v0.z * s0.z + v0.w * s0.w
             + v1.x * s1.x + v1.y * s1.y + v1.z * s1.z + v1.w * s1.w;
    float pd = v0.x * d0.x + v0.y * d0.y + v0.z * d0.z + v0.w * d0.w
             + v1.x * d1.x + v1.y * d1.y + v1.z * d1.z + v1.w * d1.w;

#pragma unroll
    for (int o = 1; o < 8; o <<= 1) {
        ps += __shfl_xor_sync(0xFFFFFFFFu, ps, o);
        pd += __shfl_xor_sync(0xFFFFFFFFu, pd, o);
    }
    if ((lane & 7) == 0) {
        int hd = lane >> 3;
        g_es[w * Hh + hd] = ps;
        g_ed[w * Hh + hd] = pd;
    }
}

// ---------------- GAT aggregation: warp per dst node -----------------
__global__ void __launch_bounds__(256) k_agg(const float* __restrict__ bias) {
    int w = (blockIdx.x * blockDim.x + threadIdx.x) >> 5;
    if (w >= Nn) return;
    int lane = threadIdx.x & 31;

    int r0 = g_off[w];
    int r1 = g_off[w + 1];
    float4 ed4 = *(const float4*)(g_ed + w * Hh);

    // pass 1: per-head max of leaky_relu(es[src]+ed[dst])
    float m0 = -3.0e38f, m1 = -3.0e38f, m2 = -3.0e38f, m3 = -3.0e38f;
    for (int i = r0 + lane; i < r1; i += 32) {
        int s = g_csr[i];
        float4 e4 = *(const float4*)(g_es + s * Hh);
        m0 = fmaxf(m0, lrelu(e4.x + ed4.x));
        m1 = fmaxf(m1, lrelu(e4.y + ed4.y));
        m2 = fmaxf(m2, lrelu(e4.z + ed4.z));
        m3 = fmaxf(m3, lrelu(e4.w + ed4.w));
    }
#pragma unroll
    for (int o = 16; o > 0; o >>= 1) {
        m0 = fmaxf(m0, __shfl_xor_sync(0xFFFFFFFFu, m0, o));
        m1 = fmaxf(m1, __shfl_xor_sync(0xFFFFFFFFu, m1, o));
        m2 = fmaxf(m2, __shfl_xor_sync(0xFFFFFFFFu, m2, o));
        m3 = fmaxf(m3, __shfl_xor_sync(0xFFFFFFFFu, m3, o));
    }
    if (m0 < -1.0e30f) m0 = 0.0f;   // segment_max -> where(isfinite, m, 0)
    if (m1 < -1.0e30f) m1 = 0.0f;
    if (m2 < -1.0e30f) m2 = 0.0f;
    if (m3 < -1.0e30f) m3 = 0.0f;

    int hsel = lane >> 3;  // this lane's channels [lane*8, lane*8+8) all in head hsel
    float mh  = (hsel == 0) ? m0 : (hsel == 1) ? m1 : (hsel == 2) ? m2 : m3;
    float edh = (hsel == 0) ? ed4.x : (hsel == 1) ? ed4.y : (hsel == 2) ? ed4.z : ed4.w;

    // pass 2: denominator + weighted sum of h[src]
    float a0 = 0.f, a1 = 0.f, a2 = 0.f, a3 = 0.f, a4 = 0.f, a5 = 0.f, a6 = 0.f, a7 = 0.f;
    float den = 0.f;
    for (int i = r0; i < r1; i++) {
        int s = g_csr[i];                     // broadcast load
        float esv = g_es[s * Hh + hsel];
        float t = esv + edh;
        t = (t > 0.0f) ? t : 0.2f * t;
        float wg = __expf(t - mh);
        den += wg;
        const float4* hp = (const float4*)(g_h + (size_t)s * HC + lane * 8);
        float4 v0 = hp[0], v1 = hp[1];
        a0 = fmaf(wg, v0.x, a0); a1 = fmaf(wg, v0.y, a1);
        a2 = fmaf(wg, v0.z, a2); a3 = fmaf(wg, v0.w, a3);
        a4 = fmaf(wg, v1.x, a4); a5 = fmaf(wg, v1.y, a5);
        a6 = fmaf(wg, v1.z, a6); a7 = fmaf(wg, v1.w, a7);
    }
    float inv = 1.0f / fmaxf(den, 1e-16f);
    int b0 = lane * 8;
    float* op = g_x + (size_t)w * HC + b0;
    const float4* bp4 = (const float4*)(bias + b0);
    float4 bb0 = bp4[0], bb1 = bp4[1];
    float4 o0, o1;
    o0.x = fmaxf(a0 * inv + bb0.x, 0.0f);
    o0.y = fmaxf(a1 * inv + bb0.y, 0.0f);
    o0.z = fmaxf(a2 * inv + bb0.z, 0.0f);
    o0.w = fmaxf(a3 * inv + bb0.w, 0.0f);
    o1.x = fmaxf(a4 * inv + bb1.x, 0.0f);
    o1.y = fmaxf(a5 * inv + bb1.y, 0.0f);
    o1.z = fmaxf(a6 * inv + bb1.z, 0.0f);
    o1.w = fmaxf(a7 * inv + bb1.w, 0.0f);
    *(float4*)op = o0;
    *(float4*)(op + 4) = o1;
}

// ---------------- projection + pooled sums: warp per node -----------------
__global__ void k_pool(const float* __restrict__ Wp, const int* __restrict__ batch) {
    int w = (blockIdx.x * blockDim.x + threadIdx.x) >> 5;
    if (w >= Nn) return;
    int lane = threadIdx.x & 31;

    float acc = 0.0f;
#pragma unroll
    for (int k8 = 0; k8 < 8; k8++) {
        float xv = g_x[(size_t)w * HC + k8 * 32 + lane];
#pragma unroll
        for (int j = 0; j < 32; j++) {
            float xb = __shfl_sync(0xFFFFFFFFu, xv, j);
            acc = fmaf(xb, Wp[(size_t)(k8 * 32 + j) * DOUT + lane], acc);
        }
    }
    int g = batch[w];
    atomicAdd(&g_sums[g * DOUT + lane], acc);
    if (lane == 0) atomicAdd(&g_cnt[g], 1);
}

__global__ void k_fin(float* __restrict__ out, const float* __restrict__ bp) {
    int i = blockIdx.x * blockDim.x + threadIdx.x;
    if (i >= Gg * DOUT) return;
    int g = i / DOUT, j = i % DOUT;
    out[i] = g_sums[i] / fmaxf((float)g_cnt[g], 1.0f) + bp[j];
}

// ---------------- launch ----------------
extern "C" void kernel_launch(void* const* d_in, const int* in_sizes, int n_in,
                              void* d_out, int out_size) {
    const float* x     = (const float*)d_in[0];
    const int*   ei    = (const int*)d_in[1];
    const int*   batch = (const int*)d_in[2];
    const float* W1    = (const float*)d_in[3];
    const float* as1   = (const float*)d_in[4];
    const float* ad1   = (const float*)d_in[5];
    const float* b1    = (const float*)d_in[6];
    const float* W2    = (const float*)d_in[7];
    const float* as2   = (const float*)d_in[8];
    const float* ad2   = (const float*)d_in[9];
    const float* b2    = (const float*)d_in[10];
    const float* Wp    = (const float*)d_in[11];
    const float* bp    = (const float*)d_in[12];
    float* out = (float*)d_out;

    (void)in_sizes; (void)n_in; (void)out_size;

    // CSR build (shared by both layers)
    k_zero<<<(Nn + 255) / 256, 256>>>();
    k_count<<<(ETOT + 255) / 256, 256>>>(ei);
    k_scan<<<1, 1024>>>();
    k_scatter<<<(ETOT + 255) / 256, 256>>>(ei);

    dim3 gemm_grid((Nn + BM - 1) / BM, HC / BN);  // (157, 4)
    int warp_blocks = (Nn * 32 + 255) / 256;      // 2500

    // Layer 1
    k_gemm<<<gemm_grid, 256>>>(x, W1, 1);
    k_attn<<<warp_blocks, 256>>>(as1, ad1);
    k_agg<<<warp_blocks, 256>>>(b1);

    // Layer 2 (reads g_x, writes g_h, then aggregates back into g_x)
    k_gemm<<<gemm_grid, 256>>>(nullptr, W2, 0);
    k_attn<<<warp_blocks, 256>>>(as2, ad2);
    k_agg<<<warp_blocks, 256>>>(b2);

    // Projection + mean pooling
    k_pool<<<warp_blocks, 256>>>(Wp, batch);
    k_fin<<<(Gg * DOUT + 255) / 256, 256>>>(out, bp);
}